// round 12
// baseline (speedup 1.0000x reference)
#include <cuda_runtime.h>
#include <math.h>

#define H 1024
#define L 512
#define V 50257

// ---------------- scratch layout (floats) ----------------
#define OFF_ALOG   0        // attn logits (512)
#define OFF_ATT    512      // attn_applied accumulator (1024)
#define OFF_X      1536     // GRU input x (1024)
#define OFF_GI     2560     // gi (3072)
#define OFF_GH     5632     // gh (3072)
#define OFF_HNEW   8704     // h_new (1024)
#define OFF_LOGITS 9728     // vocab logits (50257)
#define OFF_PART   59985    // MB partial exp-sums
#define OFF_LSE    60577
#define SCRATCH_FLOATS 60578

__device__ float g_scratch[SCRATCH_FLOATS];
__device__ int   g_maxbits;   // ordered-int running max of vocab logits
__device__ int   g_c1;        // gi done
__device__ int   g_c2;        // gates done
__device__ int   g_c3;        // logits done
__device__ int   g_count_ls;  // partial-sum arrivals
__device__ int   g_flag_ls;   // lse ready

__device__ __forceinline__ int f2ord(float f) {
    int i = __float_as_int(f);
    return (i >= 0) ? i : (i ^ 0x7FFFFFFF);
}
__device__ __forceinline__ float ord2f(int o) {
    return __int_as_float((o >= 0) ? o : (o ^ 0x7FFFFFFF));
}

__device__ __forceinline__ float warp_sum(float a) {
    #pragma unroll
    for (int o = 16; o; o >>= 1) a += __shfl_xor_sync(0xFFFFFFFFu, a, o);
    return a;
}

// ---- TMA bulk-copy helpers ----
__device__ __forceinline__ unsigned smem_u32(const void* p) {
    return (unsigned)__cvta_generic_to_shared(p);
}
__device__ __forceinline__ void mbar_init(unsigned mbar, unsigned count) {
    asm volatile("mbarrier.init.shared.b64 [%0], %1;" :: "r"(mbar), "r"(count) : "memory");
}
__device__ __forceinline__ void mbar_expect_tx(unsigned mbar, unsigned bytes) {
    asm volatile("mbarrier.arrive.expect_tx.shared.b64 _, [%0], %1;"
                 :: "r"(mbar), "r"(bytes) : "memory");
}
__device__ __forceinline__ void bulk_g2s(unsigned dst, const void* src,
                                         unsigned bytes, unsigned mbar) {
    asm volatile("cp.async.bulk.shared::cta.global.mbarrier::complete_tx::bytes "
                 "[%0], [%1], %2, [%3];"
                 :: "r"(dst), "l"(src), "r"(bytes), "r"(mbar) : "memory");
}
__device__ __forceinline__ void mbar_wait(unsigned mbar, unsigned parity) {
    unsigned done;
    do {
        asm volatile("{\n\t.reg .pred p;\n\t"
                     "mbarrier.try_wait.parity.acquire.cta.shared::cta.b64 p, [%1], %2;\n\t"
                     "selp.b32 %0, 1, 0, p;\n\t}"
                     : "=r"(done) : "r"(mbar), "r"(parity) : "memory");
    } while (!done);
}

// dot of 8 front-batched float4 (1024 floats) against smem slice
__device__ __forceinline__ float dot8(const float4* __restrict__ wr,
                                      const float4* __restrict__ v4,
                                      int lane) {
    float4 w0 = __ldcs(wr + lane);
    float4 w1 = __ldcs(wr + lane + 32);
    float4 w2 = __ldcs(wr + lane + 64);
    float4 w3 = __ldcs(wr + lane + 96);
    float4 w4 = __ldcs(wr + lane + 128);
    float4 w5 = __ldcs(wr + lane + 160);
    float4 w6 = __ldcs(wr + lane + 192);
    float4 w7 = __ldcs(wr + lane + 224);
    float4 x0 = v4[lane],       x1 = v4[lane + 32];
    float4 x2 = v4[lane + 64],  x3 = v4[lane + 96];
    float4 x4 = v4[lane + 128], x5 = v4[lane + 160];
    float4 x6 = v4[lane + 192], x7 = v4[lane + 224];
    float a = 0.f;
    a += w0.x*x0.x + w0.y*x0.y + w0.z*x0.z + w0.w*x0.w;
    a += w1.x*x1.x + w1.y*x1.y + w1.z*x1.z + w1.w*x1.w;
    a += w2.x*x2.x + w2.y*x2.y + w2.z*x2.z + w2.w*x2.w;
    a += w3.x*x3.x + w3.y*x3.y + w3.z*x3.z + w3.w*x3.w;
    a += w4.x*x4.x + w4.y*x4.y + w4.z*x4.z + w4.w*x4.w;
    a += w5.x*x5.x + w5.y*x5.y + w5.z*x5.z + w5.w*x5.w;
    a += w6.x*x6.x + w6.y*x6.y + w6.z*x6.z + w6.w*x6.w;
    a += w7.x*x7.x + w7.y*x7.y + w7.z*x7.z + w7.w*x7.w;
    return a;
}

// dot of 4 front-batched float4 (512 floats)
__device__ __forceinline__ float dot4(const float4* __restrict__ wr,
                                      const float4* __restrict__ v4,
                                      int lane) {
    float4 w0 = __ldcs(wr + lane);
    float4 w1 = __ldcs(wr + lane + 32);
    float4 w2 = __ldcs(wr + lane + 64);
    float4 w3 = __ldcs(wr + lane + 96);
    float4 x0 = v4[lane],      x1 = v4[lane + 32];
    float4 x2 = v4[lane + 64], x3 = v4[lane + 96];
    float a = 0.f;
    a += w0.x*x0.x + w0.y*x0.y + w0.z*x0.z + w0.w*x0.w;
    a += w1.x*x1.x + w1.y*x1.y + w1.z*x1.z + w1.w*x1.w;
    a += w2.x*x2.x + w2.y*x2.y + w2.z*x2.z + w2.w*x2.w;
    a += w3.x*x3.x + w3.y*x3.y + w3.z*x3.z + w3.w*x3.w;
    return a;
}

// ---------------- N1: attn logits (blocks 0-127) + gh GEMV (blocks 128-895) ----------------
__global__ void __launch_bounds__(256)
k_attn_gh(const float* __restrict__ attn_W, const float* __restrict__ attn_b,
          const float* __restrict__ W_hh, const float* __restrict__ b_hh,
          const int* __restrict__ idx, const float* __restrict__ hidden,
          const float* __restrict__ emb) {
    __shared__ float sv[2 * H];
    __shared__ float spart[8];
    int t = threadIdx.x, bid = blockIdx.x;
    int warp = t >> 5, lane = t & 31;

    if (bid < 128) {
        int row_e = idx[0];
        #pragma unroll
        for (int i = t; i < 512; i += 256) {
            ((float4*)sv)[i] = (i < 256)
                ? ((const float4*)(emb + (size_t)row_e * H))[i]
                : ((const float4*)hidden)[i - 256];
        }
    } else {
        ((float4*)sv)[t] = ((const float4*)hidden)[t];
    }
    if (bid == 0) {
        #pragma unroll
        for (int i = t; i < H; i += 256) g_scratch[OFF_ATT + i] = 0.f;
        if (t == 0) {
            g_maxbits = 0x80000000;
            g_c1 = 0; g_c2 = 0; g_c3 = 0;
            g_count_ls = 0; g_flag_ls = 0;
        }
    }
    __syncthreads();

    if (bid < 128) {
        int row  = bid * 4 + (warp >> 1);
        int half = warp & 1;
        const float4* wr = (const float4*)(attn_W + (size_t)row * 2 * H + half * H);
        float acc = warp_sum(dot8(wr, (const float4*)(sv + half * H), lane));
        if (lane == 0) spart[warp] = acc;
        __syncthreads();
        if (t < 4) {
            int r = bid * 4 + t;
            g_scratch[OFF_ALOG + r] = spart[2 * t] + spart[2 * t + 1] + attn_b[r];
        }
    } else {
        int row  = (bid - 128) * 4 + (warp >> 1);
        int half = warp & 1;
        const float4* wr = (const float4*)(W_hh + (size_t)row * H + half * 512);
        float acc = warp_sum(dot4(wr, (const float4*)(sv + half * 512), lane));
        if (lane == 0) spart[warp] = acc;
        __syncthreads();
        if (t < 4) {
            int r = (bid - 128) * 4 + t;
            g_scratch[OFF_GH + r] = spart[2 * t] + spart[2 * t + 1] + b_hh[r];
        }
    }
}

// ---------------- N2: per-block softmax(512) + attn_applied partials ----------------
__global__ void __launch_bounds__(256)
k_apply(const float* __restrict__ enc, float* __restrict__ out_full) {
    __shared__ float aw[512];
    __shared__ float sred[256];
    int t = threadIdx.x;
    float v0 = g_scratch[OFF_ALOG + t];
    float v1 = g_scratch[OFF_ALOG + 256 + t];
    sred[t] = fmaxf(v0, v1);
    __syncthreads();
    #pragma unroll
    for (int s = 128; s > 0; s >>= 1) {
        if (t < s) sred[t] = fmaxf(sred[t], sred[t + s]);
        __syncthreads();
    }
    float mx = sred[0];
    __syncthreads();
    float e0 = expf(v0 - mx), e1 = expf(v1 - mx);
    sred[t] = e0 + e1;
    __syncthreads();
    #pragma unroll
    for (int s = 128; s > 0; s >>= 1) {
        if (t < s) sred[t] += sred[t + s];
        __syncthreads();
    }
    float inv = 1.f / sred[0];
    aw[t] = e0 * inv; aw[256 + t] = e1 * inv;
    __syncthreads();
    if (blockIdx.x == 0 && blockIdx.y == 0) {
        out_full[V + H + t]       = aw[t];
        out_full[V + H + 256 + t] = aw[256 + t];
    }
    int col  = blockIdx.x * 256 + t;
    int base = blockIdx.y * 32;
    float s = 0.f;
    #pragma unroll
    for (int l = 0; l < 32; l++)
        s += aw[base + l] * __ldcs(enc + (size_t)(base + l) * H + col);
    atomicAdd(&g_scratch[OFF_ATT + col], s);
}

// ---------------- N3: x = relu(cat(emb[idx], attn_applied) @ comb_W.T + b) ----------------
__global__ void __launch_bounds__(256)
k_comb(const float* __restrict__ comb_W, const float* __restrict__ comb_b,
       const int* __restrict__ idx, const float* __restrict__ emb) {
    __shared__ float sv[2 * H];
    __shared__ float spart[8];
    int t = threadIdx.x;
    int warp = t >> 5, lane = t & 31;
    int row_e = idx[0];
    #pragma unroll
    for (int i = t; i < 512; i += 256) {
        ((float4*)sv)[i] = (i < 256)
            ? ((const float4*)(emb + (size_t)row_e * H))[i]
            : ((const float4*)(g_scratch + OFF_ATT))[i - 256];
    }
    __syncthreads();
    int row  = blockIdx.x * 4 + (warp >> 1);
    int half = warp & 1;
    const float4* wr = (const float4*)(comb_W + (size_t)row * 2 * H + half * H);
    float acc = warp_sum(dot8(wr, (const float4*)(sv + half * H), lane));
    if (lane == 0) spart[warp] = acc;
    __syncthreads();
    if (t < 4) {
        int r = blockIdx.x * 4 + t;
        g_scratch[OFF_X + r] = fmaxf(spart[2 * t] + spart[2 * t + 1] + comb_b[r], 0.f);
    }
}

// ---------------- N4: mega kernel — gi -> gates -> vocab(TMA) -> log-softmax ----------------
// 592 blocks = 148 SMs x 4, __launch_bounds__(256,4): all resident (spin-safe).
#define MB 592
#define NTILES ((V + 3) / 4)   // 12565 tiles of 4 rows
__global__ void __launch_bounds__(256, 4)
k_mega(const float* __restrict__ W_ih, const float* __restrict__ b_ih,
       const float* __restrict__ hidden,
       const float* __restrict__ out_W, const float* __restrict__ out_b,
       float* __restrict__ out_full) {
    __shared__ __align__(128) float tiles[2][4 * H];   // 2 x 16 KB
    __shared__ __align__(16) unsigned long long mbar[2];
    __shared__ float hv[H];
    __shared__ float spart[8];
    __shared__ float smax[4];
    __shared__ float sm[256];
    __shared__ int s_last;
    int t = threadIdx.x, warp = t >> 5, lane = t & 31;
    int gw = blockIdx.x * 8 + warp;

    if (t == 0) { mbar_init(smem_u32(&mbar[0]), 1); mbar_init(smem_u32(&mbar[1]), 1); }

    // ---- phase 1: gi = x @ W_ih.T + b_ih (one row per warp, rows 0..3071) ----
    ((float4*)hv)[t] = ((const float4*)(g_scratch + OFF_X))[t];
    __syncthreads();
    if (gw < 3 * H) {
        const float4* wr = (const float4*)(W_ih + (size_t)gw * H);
        float acc = warp_sum(dot8(wr, (const float4*)hv, lane));
        if (lane == 0) g_scratch[OFF_GI + gw] = acc + b_ih[gw];
    }
    __threadfence();
    __syncthreads();
    if (t == 0) atomicAdd(&g_c1, 1);

    // ---- phase 2: GRU gates by blocks 0-3 ----
    if (blockIdx.x < 4) {
        if (t == 0) { while (atomicAdd(&g_c1, 0) < MB) { } __threadfence(); }
        __syncthreads();
        int j = blockIdx.x * 256 + t;
        float gir = g_scratch[OFF_GI + j],       ghr = g_scratch[OFF_GH + j];
        float giz = g_scratch[OFF_GI + H + j],   ghz = g_scratch[OFF_GH + H + j];
        float gin = g_scratch[OFF_GI + 2*H + j], ghn = g_scratch[OFF_GH + 2*H + j];
        float r = 1.f / (1.f + expf(-(gir + ghr)));
        float z = 1.f / (1.f + expf(-(giz + ghz)));
        float n = tanhf(gin + r * ghn);
        float hn = (1.f - z) * n + z * hidden[j];
        g_scratch[OFF_HNEW + j] = hn;
        out_full[V + j] = hn;                 // second output
        __threadfence();
        __syncthreads();
        if (t == 0) atomicAdd(&g_c2, 1);
    }
    if (t == 0) { while (atomicAdd(&g_c2, 0) < 4) { } __threadfence(); }
    __syncthreads();

    // ---- phase 3: vocab logits via TMA bulk double-buffer ----
    ((float4*)hv)[t] = ((const float4*)(g_scratch + OFF_HNEW))[t];
    __syncthreads();
    unsigned mb0 = smem_u32(&mbar[0]), mb1 = smem_u32(&mbar[1]);
    unsigned tb0 = smem_u32(&tiles[0][0]), tb1 = smem_u32(&tiles[1][0]);
    // prologue: issue first two tiles
    if (t == 0) {
        long tl0 = blockIdx.x;
        if (tl0 < NTILES) {
            unsigned bytes = (unsigned)(min(4, (int)(V - tl0 * 4))) * 4096u;
            mbar_expect_tx(mb0, bytes);
            bulk_g2s(tb0, out_W + tl0 * 4 * H, bytes, mb0);
        }
        long tl1 = blockIdx.x + MB;
        if (tl1 < NTILES) {
            unsigned bytes = (unsigned)(min(4, (int)(V - tl1 * 4))) * 4096u;
            mbar_expect_tx(mb1, bytes);
            bulk_g2s(tb1, out_W + tl1 * 4 * H, bytes, mb1);
        }
    }
    float lmax = -INFINITY;
    unsigned ph0 = 0, ph1 = 0;
    int lrow = warp >> 1, half = warp & 1;
    long k = 0;
    for (long tl = blockIdx.x; tl < NTILES; tl += MB, k++) {
        int buf = (int)(k & 1);
        unsigned mb = buf ? mb1 : mb0;
        unsigned par = buf ? ph1 : ph0;
        mbar_wait(mb, par);
        if (buf) ph1 ^= 1; else ph0 ^= 1;

        long row = tl * 4 + lrow;
        float acc = 0.f;
        if (row < V) {
            const float4* wsm = (const float4*)(&tiles[buf][lrow * H + half * 512]);
            const float4* xsm = (const float4*)(hv + half * 512);
            float4 w0 = wsm[lane], w1 = wsm[lane + 32], w2 = wsm[lane + 64], w3 = wsm[lane + 96];
            float4 x0 = xsm[lane], x1 = xsm[lane + 32], x2 = xsm[lane + 64], x3 = xsm[lane + 96];
            float a0 = w0.x*x0.x + w0.y*x0.y + w0.z*x0.z + w0.w*x0.w;
            float a1 = w1.x*x1.x + w1.y*x1.y + w1.z*x1.z + w1.w*x1.w;
            float a2 = w2.x*x2.x + w2.y*x2.y + w2.z*x2.z + w2.w*x2.w;
            float a3 = w3.x*x3.x + w3.y*x3.y + w3.z*x3.z + w3.w*x3.w;
            acc = warp_sum((a0 + a1) + (a2 + a3));
        }
        if (lane == 0) spart[warp] = acc;
        __syncthreads();
        if (t < 4) {
            long r = tl * 4 + t;
            if (r < V) {
                float v = spart[2 * t] + spart[2 * t + 1] + out_b[r];
                g_scratch[OFF_LOGITS + r] = v;
                lmax = fmaxf(lmax, v);
            }
        }
        __syncthreads();   // tile consumed; safe to reissue
        if (t == 0) {
            long nt = tl + 2 * (long)MB;
            if (nt < NTILES) {
                unsigned bytes = (unsigned)(min(4, (int)(V - nt * 4))) * 4096u;
                mbar_expect_tx(mb, bytes);
                bulk_g2s(buf ? tb1 : tb0, out_W + nt * 4 * H, bytes, mb);
            }
        }
    }
    if (t < 4) smax[t] = lmax;
    __threadfence();
    __syncthreads();
    if (t == 0) {
        float bm = fmaxf(fmaxf(smax[0], smax[1]), fmaxf(smax[2], smax[3]));
        atomicMax(&g_maxbits, f2ord(bm));
        atomicAdd(&g_c3, 1);
        while (atomicAdd(&g_c3, 0) < MB) { }
        __threadfence();
    }
    __syncthreads();

    // ---- phase 4: log-softmax ----
    float gm = ord2f(g_maxbits);
    float s = 0.f;
    for (int i = blockIdx.x * 256 + t; i < V; i += MB * 256)
        s += expf(g_scratch[OFF_LOGITS + i] - gm);
    sm[t] = s;
    __syncthreads();
    #pragma unroll
    for (int st = 128; st > 0; st >>= 1) {
        if (t < st) sm[t] += sm[t + st];
        __syncthreads();
    }
    if (t == 0) {
        g_scratch[OFF_PART + blockIdx.x] = sm[0];
        __threadfence();
        int old = atomicAdd(&g_count_ls, 1);
        s_last = (old == MB - 1);
    }
    __syncthreads();
    if (s_last) {
        float p = 0.f;
        for (int i = t; i < MB; i += 256) p += g_scratch[OFF_PART + i];
        sm[t] = p;
        __syncthreads();
        #pragma unroll
        for (int st = 128; st > 0; st >>= 1) {
            if (t < st) sm[t] += sm[t + st];
            __syncthreads();
        }
        if (t == 0) {
            g_scratch[OFF_LSE] = gm + logf(sm[0]);
            __threadfence();
            atomicExch(&g_flag_ls, 1);
        }
    }
    if (t == 0) { while (atomicAdd(&g_flag_ls, 0) == 0) { } __threadfence(); }
    __syncthreads();
    float lse = g_scratch[OFF_LSE];
    for (int i = blockIdx.x * 256 + t; i < V; i += MB * 256)
        out_full[i] = g_scratch[OFF_LOGITS + i] - lse;
}

// ---------------- launch: 4 graph nodes ----------------
extern "C" void kernel_launch(void* const* d_in, const int* in_sizes, int n_in,
                              void* d_out, int out_size) {
    const int*   input_idx = (const int*)  d_in[0];
    const float* hidden    = (const float*)d_in[1];
    const float* enc       = (const float*)d_in[2];
    const float* emb       = (const float*)d_in[3];
    const float* attn_W    = (const float*)d_in[4];
    const float* attn_b    = (const float*)d_in[5];
    const float* comb_W    = (const float*)d_in[6];
    const float* comb_b    = (const float*)d_in[7];
    const float* W_ih      = (const float*)d_in[8];
    const float* W_hh      = (const float*)d_in[9];
    const float* b_ih      = (const float*)d_in[10];
    const float* b_hh      = (const float*)d_in[11];
    const float* out_W     = (const float*)d_in[12];
    const float* out_b     = (const float*)d_in[13];
    float* out = (float*)d_out;

    k_attn_gh<<<896, 256>>>(attn_W, attn_b, W_hh, b_hh, input_idx, hidden, emb);
    k_apply  <<<dim3(4, 16), 256>>>(enc, out);
    k_comb   <<<256, 256>>>(comb_W, comb_b, input_idx, emb);
    k_mega   <<<MB, 256>>>(W_ih, b_ih, hidden, out_W, out_b, out);
}

// round 13
// speedup vs baseline: 1.0271x; 1.0271x over previous
#include <cuda_runtime.h>
#include <math.h>

#define H 1024
#define L 512
#define V 50257

// ---------------- scratch layout (floats) ----------------
#define OFF_ALOG   0        // attn logits (512)
#define OFF_ATT    512      // attn_applied accumulator (1024)
#define OFF_X      1536     // GRU input x (1024)
#define OFF_GI     2560     // gi (3072)
#define OFF_GH     5632     // gh (3072)
#define OFF_HNEW   8704     // h_new (1024)
#define OFF_LOGITS 9728     // vocab logits (50257)
#define OFF_PART   59985    // MB partial exp-sums
#define OFF_LSE    60429
#define SCRATCH_FLOATS 60432

__device__ float g_scratch[SCRATCH_FLOATS];
__device__ int   g_maxbits;   // ordered-int running max of vocab logits
__device__ int   g_c1;        // mega: gi done
__device__ int   g_c2;        // mega: gates done
__device__ int   g_c3;        // mega: logits done
__device__ int   g_count_ls;  // mega: partial-sum arrivals
__device__ int   g_flag_ls;   // mega: lse ready
__device__ int   g_fa;        // front: attn/gh done
__device__ int   g_fb;        // front: apply done
__device__ int   g_fe;        // front: end counter (self-reset)

__device__ __forceinline__ int f2ord(float f) {
    int i = __float_as_int(f);
    return (i >= 0) ? i : (i ^ 0x7FFFFFFF);
}
__device__ __forceinline__ float ord2f(int o) {
    return __int_as_float((o >= 0) ? o : (o ^ 0x7FFFFFFF));
}

__device__ __forceinline__ float warp_sum(float a) {
    #pragma unroll
    for (int o = 16; o; o >>= 1) a += __shfl_xor_sync(0xFFFFFFFFu, a, o);
    return a;
}

// dot of 8 front-batched float4 (1024 floats) against smem slice
__device__ __forceinline__ float dot8(const float4* __restrict__ wr,
                                      const float4* __restrict__ v4,
                                      int lane) {
    float4 w0 = __ldcs(wr + lane);
    float4 w1 = __ldcs(wr + lane + 32);
    float4 w2 = __ldcs(wr + lane + 64);
    float4 w3 = __ldcs(wr + lane + 96);
    float4 w4 = __ldcs(wr + lane + 128);
    float4 w5 = __ldcs(wr + lane + 160);
    float4 w6 = __ldcs(wr + lane + 192);
    float4 w7 = __ldcs(wr + lane + 224);
    float4 x0 = v4[lane],       x1 = v4[lane + 32];
    float4 x2 = v4[lane + 64],  x3 = v4[lane + 96];
    float4 x4 = v4[lane + 128], x5 = v4[lane + 160];
    float4 x6 = v4[lane + 192], x7 = v4[lane + 224];
    float a = 0.f;
    a += w0.x*x0.x + w0.y*x0.y + w0.z*x0.z + w0.w*x0.w;
    a += w1.x*x1.x + w1.y*x1.y + w1.z*x1.z + w1.w*x1.w;
    a += w2.x*x2.x + w2.y*x2.y + w2.z*x2.z + w2.w*x2.w;
    a += w3.x*x3.x + w3.y*x3.y + w3.z*x3.z + w3.w*x3.w;
    a += w4.x*x4.x + w4.y*x4.y + w4.z*x4.z + w4.w*x4.w;
    a += w5.x*x5.x + w5.y*x5.y + w5.z*x5.z + w5.w*x5.w;
    a += w6.x*x6.x + w6.y*x6.y + w6.z*x6.z + w6.w*x6.w;
    a += w7.x*x7.x + w7.y*x7.y + w7.z*x7.z + w7.w*x7.w;
    return a;
}

// dot of 4 front-batched float4 (512 floats)
__device__ __forceinline__ float dot4(const float4* __restrict__ wr,
                                      const float4* __restrict__ v4,
                                      int lane) {
    float4 w0 = __ldcs(wr + lane);
    float4 w1 = __ldcs(wr + lane + 32);
    float4 w2 = __ldcs(wr + lane + 64);
    float4 w3 = __ldcs(wr + lane + 96);
    float4 x0 = v4[lane],      x1 = v4[lane + 32];
    float4 x2 = v4[lane + 64], x3 = v4[lane + 96];
    float a = 0.f;
    a += w0.x*x0.x + w0.y*x0.y + w0.z*x0.z + w0.w*x0.w;
    a += w1.x*x1.x + w1.y*x1.y + w1.z*x1.z + w1.w*x1.w;
    a += w2.x*x2.x + w2.y*x2.y + w2.z*x2.z + w2.w*x2.w;
    a += w3.x*x3.x + w3.y*x3.y + w3.z*x3.z + w3.w*x3.w;
    return a;
}

// ---------------- N1: front persistent kernel — attn+gh -> apply -> comb ----------------
// 592 blocks = 148 x 4, __launch_bounds__(256,4): all resident (spin-safe).
#define FB 592
__global__ void __launch_bounds__(256, 4)
k_front(const float* __restrict__ attn_W, const float* __restrict__ attn_b,
        const float* __restrict__ W_hh, const float* __restrict__ b_hh,
        const float* __restrict__ comb_W, const float* __restrict__ comb_b,
        const int* __restrict__ idx, const float* __restrict__ hidden,
        const float* __restrict__ emb, const float* __restrict__ enc,
        float* __restrict__ out_full) {
    __shared__ float sv[2 * H];      // [emb | hidden], later [emb | attn_applied]
    __shared__ float spart[8];
    __shared__ float sred[256];
    __shared__ float aw[512];
    int t = threadIdx.x, warp = t >> 5, lane = t & 31;

    // load emb row + hidden once
    {
        int row_e = idx[0];
        #pragma unroll
        for (int i = t; i < 512; i += 256) {
            ((float4*)sv)[i] = (i < 256)
                ? ((const float4*)(emb + (size_t)row_e * H))[i]
                : ((const float4*)hidden)[i - 256];
        }
    }
    if (blockIdx.x == 0) {
        #pragma unroll
        for (int i = t; i < H; i += 256) g_scratch[OFF_ATT + i] = 0.f;
        if (t == 0) {
            g_maxbits = 0x80000000;
            g_c1 = 0; g_c2 = 0; g_c3 = 0;
            g_count_ls = 0; g_flag_ls = 0;
        }
    }
    __syncthreads();

    // ---- P1: attn logits (block-tasks 0-127) + gh (block-tasks 128-895) ----
    for (int bt = blockIdx.x; bt < 896; bt += FB) {
        if (bt < 128) {
            int row  = bt * 4 + (warp >> 1);
            int half = warp & 1;
            const float4* wr = (const float4*)(attn_W + (size_t)row * 2 * H + half * H);
            float acc = warp_sum(dot8(wr, (const float4*)(sv + half * H), lane));
            if (lane == 0) spart[warp] = acc;
            __syncthreads();
            if (t < 4) {
                int r = bt * 4 + t;
                g_scratch[OFF_ALOG + r] = spart[2 * t] + spart[2 * t + 1] + attn_b[r];
            }
        } else {
            int row  = (bt - 128) * 4 + (warp >> 1);
            int half = warp & 1;
            const float4* wr = (const float4*)(W_hh + (size_t)row * H + half * 512);
            float acc = warp_sum(dot4(wr, (const float4*)(sv + H + half * 512), lane));
            if (lane == 0) spart[warp] = acc;
            __syncthreads();
            if (t < 4) {
                int r = (bt - 128) * 4 + t;
                g_scratch[OFF_GH + r] = spart[2 * t] + spart[2 * t + 1] + b_hh[r];
            }
        }
        __syncthreads();
    }
    // barrier A
    __threadfence();
    if (t == 0) { atomicAdd(&g_fa, 1); while (atomicAdd(&g_fa, 0) < FB) { } __threadfence(); }
    __syncthreads();

    // ---- P2: apply (blocks 0-63): softmax(512) + attn_applied partials ----
    if (blockIdx.x < 64) {
        int bx = blockIdx.x & 3;         // col group 0..3
        int by = blockIdx.x >> 2;        // L chunk 0..15
        float v0 = g_scratch[OFF_ALOG + t];
        float v1 = g_scratch[OFF_ALOG + 256 + t];
        sred[t] = fmaxf(v0, v1);
        __syncthreads();
        #pragma unroll
        for (int s = 128; s > 0; s >>= 1) {
            if (t < s) sred[t] = fmaxf(sred[t], sred[t + s]);
            __syncthreads();
        }
        float mx = sred[0];
        __syncthreads();
        float e0 = expf(v0 - mx), e1 = expf(v1 - mx);
        sred[t] = e0 + e1;
        __syncthreads();
        #pragma unroll
        for (int s = 128; s > 0; s >>= 1) {
            if (t < s) sred[t] += sred[t + s];
            __syncthreads();
        }
        float inv = 1.f / sred[0];
        aw[t] = e0 * inv; aw[256 + t] = e1 * inv;
        __syncthreads();
        if (blockIdx.x == 0) {
            out_full[V + H + t]       = aw[t];
            out_full[V + H + 256 + t] = aw[256 + t];
        }
        int col  = bx * 256 + t;
        int base = by * 32;
        float s = 0.f;
        #pragma unroll
        for (int l = 0; l < 32; l++)
            s += aw[base + l] * __ldcs(enc + (size_t)(base + l) * H + col);
        atomicAdd(&g_scratch[OFF_ATT + col], s);
    }
    // barrier B
    __threadfence();
    if (t == 0) { atomicAdd(&g_fb, 1); while (atomicAdd(&g_fb, 0) < FB) { } __threadfence(); }
    __syncthreads();

    // ---- P3: comb (blocks 0-255): x = relu(cat(emb, att) @ comb_W.T + b) ----
    if (blockIdx.x < 256) {
        // emb still in sv[0:1024]; refresh second half with attn_applied
        #pragma unroll
        for (int i = t; i < 256; i += 256)
            ((float4*)(sv + H))[i] = ((const float4*)(g_scratch + OFF_ATT))[i];
        __syncthreads();
        int row  = blockIdx.x * 4 + (warp >> 1);
        int half = warp & 1;
        const float4* wr = (const float4*)(comb_W + (size_t)row * 2 * H + half * H);
        float acc = warp_sum(dot8(wr, (const float4*)(sv + half * H), lane));
        if (lane == 0) spart[warp] = acc;
        __syncthreads();
        if (t < 4) {
            int r = blockIdx.x * 4 + t;
            g_scratch[OFF_X + r] = fmaxf(spart[2 * t] + spart[2 * t + 1] + comb_b[r], 0.f);
        }
    }
    // end barrier + self-reset of front counters (last block only)
    __threadfence();
    __syncthreads();
    if (t == 0) {
        int old = atomicAdd(&g_fe, 1);
        if (old == FB - 1) { g_fa = 0; g_fb = 0; g_fe = 0; __threadfence(); }
    }
}

// ---------------- N2: mega kernel — gi -> gates -> vocab -> log-softmax ----------------
// 444 blocks = 148 SMs x 3; __launch_bounds__(256,3) guarantees all resident.
#define MB 444
#define MW (MB * 8)    // 3552 warps
__global__ void __launch_bounds__(256, 3)
k_mega(const float* __restrict__ W_ih, const float* __restrict__ b_ih,
       const float* __restrict__ hidden,
       const float* __restrict__ out_W, const float* __restrict__ out_b,
       float* __restrict__ out_full) {
    __shared__ float sbuf[H];
    __shared__ float smax[8];
    __shared__ int s_last;
    int t = threadIdx.x, warp = t >> 5, lane = t & 31;
    int gw = blockIdx.x * 8 + warp;

    // ---- phase 1: gi = x @ W_ih.T + b_ih (one row per warp, rows 0..3071) ----
    ((float4*)sbuf)[t] = ((const float4*)(g_scratch + OFF_X))[t];
    __syncthreads();
    if (gw < 3 * H) {
        const float4* wr = (const float4*)(W_ih + (size_t)gw * H);
        float acc = warp_sum(dot8(wr, (const float4*)sbuf, lane));
        if (lane == 0) g_scratch[OFF_GI + gw] = acc + b_ih[gw];
    }
    __threadfence();
    __syncthreads();
    if (t == 0) atomicAdd(&g_c1, 1);

    // ---- phase 2: GRU gates by blocks 0-3 ----
    if (blockIdx.x < 4) {
        if (t == 0) { while (atomicAdd(&g_c1, 0) < MB) { } __threadfence(); }
        __syncthreads();
        int j = blockIdx.x * 256 + t;
        float gir = g_scratch[OFF_GI + j],       ghr = g_scratch[OFF_GH + j];
        float giz = g_scratch[OFF_GI + H + j],   ghz = g_scratch[OFF_GH + H + j];
        float gin = g_scratch[OFF_GI + 2*H + j], ghn = g_scratch[OFF_GH + 2*H + j];
        float r = 1.f / (1.f + expf(-(gir + ghr)));
        float z = 1.f / (1.f + expf(-(giz + ghz)));
        float n = tanhf(gin + r * ghn);
        float hn = (1.f - z) * n + z * hidden[j];
        g_scratch[OFF_HNEW + j] = hn;
        out_full[V + j] = hn;                 // second output
        __threadfence();
        __syncthreads();
        if (t == 0) atomicAdd(&g_c2, 1);
    }
    if (t == 0) { while (atomicAdd(&g_c2, 0) < 4) { } __threadfence(); }
    __syncthreads();

    // ---- phase 3: vocab logits, register-pipelined prefetch ----
    ((float4*)sbuf)[t] = ((const float4*)(g_scratch + OFF_HNEW))[t];
    __syncthreads();
    const float4* v4 = (const float4*)sbuf;
    float m = -INFINITY;
    int row = gw;
    float4 cur[8], nxt[8];
    {
        const float4* wr = (const float4*)(out_W + (size_t)row * H);
        #pragma unroll
        for (int k = 0; k < 8; k++) cur[k] = __ldcs(wr + lane + 32 * k);
    }
    while (row < V) {
        int nrow = row + MW;
        int prow = (nrow < V) ? nrow : 0;      // clamped prefetch (harmless)
        const float4* wn = (const float4*)(out_W + (size_t)prow * H);
        #pragma unroll
        for (int k = 0; k < 8; k++) nxt[k] = __ldcs(wn + lane + 32 * k);

        float a0 = 0.f, a1 = 0.f, a2 = 0.f, a3 = 0.f;
        #pragma unroll
        for (int k = 0; k < 8; k += 4) {
            float4 x0 = v4[lane + 32 * k],       x1 = v4[lane + 32 * (k + 1)];
            float4 x2 = v4[lane + 32 * (k + 2)], x3 = v4[lane + 32 * (k + 3)];
            a0 += cur[k].x*x0.x + cur[k].y*x0.y + cur[k].z*x0.z + cur[k].w*x0.w;
            a1 += cur[k+1].x*x1.x + cur[k+1].y*x1.y + cur[k+1].z*x1.z + cur[k+1].w*x1.w;
            a2 += cur[k+2].x*x2.x + cur[k+2].y*x2.y + cur[k+2].z*x2.z + cur[k+2].w*x2.w;
            a3 += cur[k+3].x*x3.x + cur[k+3].y*x3.y + cur[k+3].z*x3.z + cur[k+3].w*x3.w;
        }
        float acc = warp_sum((a0 + a1) + (a2 + a3));
        if (lane == 0) {
            float r = acc + out_b[row];
            g_scratch[OFF_LOGITS + row] = r;
            m = fmaxf(m, r);
        }
        #pragma unroll
        for (int k = 0; k < 8; k++) cur[k] = nxt[k];
        row = nrow;
    }
    if (lane == 0) smax[warp] = m;
    __threadfence();
    __syncthreads();
    if (t == 0) {
        float bm = smax[0];
        #pragma unroll
        for (int w = 1; w < 8; w++) bm = fmaxf(bm, smax[w]);
        atomicMax(&g_maxbits, f2ord(bm));
        atomicAdd(&g_c3, 1);
        while (atomicAdd(&g_c3, 0) < MB) { }
        __threadfence();
    }
    __syncthreads();

    // ---- phase 4: log-softmax ----
    float gm = ord2f(g_maxbits);
    {
        __shared__ float sm[256];
        float s = 0.f;
        for (int i = blockIdx.x * 256 + t; i < V; i += MB * 256)
            s += expf(g_scratch[OFF_LOGITS + i] - gm);
        sm[t] = s;
        __syncthreads();
        #pragma unroll
        for (int st = 128; st > 0; st >>= 1) {
            if (t < st) sm[t] += sm[t + st];
            __syncthreads();
        }
        if (t == 0) {
            g_scratch[OFF_PART + blockIdx.x] = sm[0];
            __threadfence();
            int old = atomicAdd(&g_count_ls, 1);
            s_last = (old == MB - 1);
        }
        __syncthreads();
        if (s_last) {
            float p = 0.f;
            for (int i = t; i < MB; i += 256) p += g_scratch[OFF_PART + i];
            sm[t] = p;
            __syncthreads();
            #pragma unroll
            for (int st = 128; st > 0; st >>= 1) {
                if (t < st) sm[t] += sm[t + st];
                __syncthreads();
            }
            if (t == 0) {
                g_scratch[OFF_LSE] = gm + logf(sm[0]);
                __threadfence();
                atomicExch(&g_flag_ls, 1);
            }
        }
        if (t == 0) { while (atomicAdd(&g_flag_ls, 0) == 0) { } __threadfence(); }
        __syncthreads();
        float lse = g_scratch[OFF_LSE];
        for (int i = blockIdx.x * 256 + t; i < V; i += MB * 256)
            out_full[i] = g_scratch[OFF_LOGITS + i] - lse;
    }
}

// ---------------- launch: 2 graph nodes ----------------
extern "C" void kernel_launch(void* const* d_in, const int* in_sizes, int n_in,
                              void* d_out, int out_size) {
    const int*   input_idx = (const int*)  d_in[0];
    const float* hidden    = (const float*)d_in[1];
    const float* enc       = (const float*)d_in[2];
    const float* emb       = (const float*)d_in[3];
    const float* attn_W    = (const float*)d_in[4];
    const float* attn_b    = (const float*)d_in[5];
    const float* comb_W    = (const float*)d_in[6];
    const float* comb_b    = (const float*)d_in[7];
    const float* W_ih      = (const float*)d_in[8];
    const float* W_hh      = (const float*)d_in[9];
    const float* b_ih      = (const float*)d_in[10];
    const float* b_hh      = (const float*)d_in[11];
    const float* out_W     = (const float*)d_in[12];
    const float* out_b     = (const float*)d_in[13];
    float* out = (float*)d_out;

    k_front<<<FB, 256>>>(attn_W, attn_b, W_hh, b_hh, comb_W, comb_b,
                         input_idx, hidden, emb, enc, out);
    k_mega <<<MB, 256>>>(W_ih, b_ih, hidden, out_W, out_b, out);
}

// round 14
// speedup vs baseline: 1.0870x; 1.0584x over previous
#include <cuda_runtime.h>
#include <math.h>

#define H 1024
#define L 512
#define V 50257

// ---------------- scratch layout (floats) ----------------
#define OFF_ALOG   0        // attn logits (512)
#define OFF_ATT    512      // attn_applied accumulator (1024)
#define OFF_X      1536     // GRU input x (1024)
#define OFF_GI     2560     // gi (3072)
#define OFF_GH     5632     // gh (3072)
#define OFF_HNEW   8704     // h_new (1024)
#define OFF_LOGITS 9728     // vocab logits (50257)
#define OFF_PART   59985    // MB partial exp-sums
#define OFF_LSE    60429
#define SCRATCH_FLOATS 60432

__device__ float g_scratch[SCRATCH_FLOATS];
__device__ int   g_maxbits;   // ordered-int running max of vocab logits
__device__ int   g_c1;        // gi done
__device__ int   g_c2;        // gates done
__device__ int   g_c3;        // logits done
__device__ int   g_count_ls;  // partial-sum arrivals
__device__ int   g_flag_ls;   // lse ready

__device__ __forceinline__ int f2ord(float f) {
    int i = __float_as_int(f);
    return (i >= 0) ? i : (i ^ 0x7FFFFFFF);
}
__device__ __forceinline__ float ord2f(int o) {
    return __int_as_float((o >= 0) ? o : (o ^ 0x7FFFFFFF));
}

// cheap spin poll: plain volatile L2 read instead of RMW atomic
__device__ __forceinline__ int vpoll(const int* p) {
    int v;
    asm volatile("ld.volatile.global.s32 %0, [%1];" : "=r"(v) : "l"(p));
    return v;
}

__device__ __forceinline__ float warp_sum(float a) {
    #pragma unroll
    for (int o = 16; o; o >>= 1) a += __shfl_xor_sync(0xFFFFFFFFu, a, o);
    return a;
}

// dot of 8 front-batched float4 (1024 floats) against smem slice
__device__ __forceinline__ float dot8(const float4* __restrict__ wr,
                                      const float4* __restrict__ v4,
                                      int lane) {
    float4 w0 = __ldcs(wr + lane);
    float4 w1 = __ldcs(wr + lane + 32);
    float4 w2 = __ldcs(wr + lane + 64);
    float4 w3 = __ldcs(wr + lane + 96);
    float4 w4 = __ldcs(wr + lane + 128);
    float4 w5 = __ldcs(wr + lane + 160);
    float4 w6 = __ldcs(wr + lane + 192);
    float4 w7 = __ldcs(wr + lane + 224);
    float4 x0 = v4[lane],       x1 = v4[lane + 32];
    float4 x2 = v4[lane + 64],  x3 = v4[lane + 96];
    float4 x4 = v4[lane + 128], x5 = v4[lane + 160];
    float4 x6 = v4[lane + 192], x7 = v4[lane + 224];
    float a = 0.f;
    a += w0.x*x0.x + w0.y*x0.y + w0.z*x0.z + w0.w*x0.w;
    a += w1.x*x1.x + w1.y*x1.y + w1.z*x1.z + w1.w*x1.w;
    a += w2.x*x2.x + w2.y*x2.y + w2.z*x2.z + w2.w*x2.w;
    a += w3.x*x3.x + w3.y*x3.y + w3.z*x3.z + w3.w*x3.w;
    a += w4.x*x4.x + w4.y*x4.y + w4.z*x4.z + w4.w*x4.w;
    a += w5.x*x5.x + w5.y*x5.y + w5.z*x5.z + w5.w*x5.w;
    a += w6.x*x6.x + w6.y*x6.y + w6.z*x6.z + w6.w*x6.w;
    a += w7.x*x7.x + w7.y*x7.y + w7.z*x7.z + w7.w*x7.w;
    return a;
}

// dot of 4 front-batched float4 (512 floats)
__device__ __forceinline__ float dot4(const float4* __restrict__ wr,
                                      const float4* __restrict__ v4,
                                      int lane) {
    float4 w0 = __ldcs(wr + lane);
    float4 w1 = __ldcs(wr + lane + 32);
    float4 w2 = __ldcs(wr + lane + 64);
    float4 w3 = __ldcs(wr + lane + 96);
    float4 x0 = v4[lane],      x1 = v4[lane + 32];
    float4 x2 = v4[lane + 64], x3 = v4[lane + 96];
    float a = 0.f;
    a += w0.x*x0.x + w0.y*x0.y + w0.z*x0.z + w0.w*x0.w;
    a += w1.x*x1.x + w1.y*x1.y + w1.z*x1.z + w1.w*x1.w;
    a += w2.x*x2.x + w2.y*x2.y + w2.z*x2.z + w2.w*x2.w;
    a += w3.x*x3.x + w3.y*x3.y + w3.z*x3.z + w3.w*x3.w;
    return a;
}

// ---------------- N1: attn logits (blocks 0-127) + gh GEMV (blocks 128-895) ----------------
__global__ void __launch_bounds__(256)
k_attn_gh(const float* __restrict__ attn_W, const float* __restrict__ attn_b,
          const float* __restrict__ W_hh, const float* __restrict__ b_hh,
          const int* __restrict__ idx, const float* __restrict__ hidden,
          const float* __restrict__ emb) {
    __shared__ float sv[2 * H];
    __shared__ float spart[8];
    int t = threadIdx.x, bid = blockIdx.x;
    int warp = t >> 5, lane = t & 31;

    if (bid < 128) {
        int row_e = idx[0];
        #pragma unroll
        for (int i = t; i < 512; i += 256) {
            ((float4*)sv)[i] = (i < 256)
                ? ((const float4*)(emb + (size_t)row_e * H))[i]
                : ((const float4*)hidden)[i - 256];
        }
    } else {
        ((float4*)sv)[t] = ((const float4*)hidden)[t];
    }
    if (bid == 0) {
        #pragma unroll
        for (int i = t; i < H; i += 256) g_scratch[OFF_ATT + i] = 0.f;
        if (t == 0) {
            g_maxbits = 0x80000000;
            g_c1 = 0; g_c2 = 0; g_c3 = 0;
            g_count_ls = 0; g_flag_ls = 0;
        }
    }
    __syncthreads();

    if (bid < 128) {
        int row  = bid * 4 + (warp >> 1);
        int half = warp & 1;
        const float4* wr = (const float4*)(attn_W + (size_t)row * 2 * H + half * H);
        float acc = warp_sum(dot8(wr, (const float4*)(sv + half * H), lane));
        if (lane == 0) spart[warp] = acc;
        __syncthreads();
        if (t < 4) {
            int r = bid * 4 + t;
            g_scratch[OFF_ALOG + r] = spart[2 * t] + spart[2 * t + 1] + attn_b[r];
        }
    } else {
        int row  = (bid - 128) * 4 + (warp >> 1);
        int half = warp & 1;
        const float4* wr = (const float4*)(W_hh + (size_t)row * H + half * 512);
        float acc = warp_sum(dot4(wr, (const float4*)(sv + half * 512), lane));
        if (lane == 0) spart[warp] = acc;
        __syncthreads();
        if (t < 4) {
            int r = (bid - 128) * 4 + t;
            g_scratch[OFF_GH + r] = spart[2 * t] + spart[2 * t + 1] + b_hh[r];
        }
    }
}

// ---------------- N2: per-block softmax(512) + attn_applied partials ----------------
__global__ void __launch_bounds__(256)
k_apply(const float* __restrict__ enc, float* __restrict__ out_full) {
    __shared__ float aw[512];
    __shared__ float sred[256];
    int t = threadIdx.x;
    float v0 = g_scratch[OFF_ALOG + t];
    float v1 = g_scratch[OFF_ALOG + 256 + t];
    sred[t] = fmaxf(v0, v1);
    __syncthreads();
    #pragma unroll
    for (int s = 128; s > 0; s >>= 1) {
        if (t < s) sred[t] = fmaxf(sred[t], sred[t + s]);
        __syncthreads();
    }
    float mx = sred[0];
    __syncthreads();
    float e0 = expf(v0 - mx), e1 = expf(v1 - mx);
    sred[t] = e0 + e1;
    __syncthreads();
    #pragma unroll
    for (int s = 128; s > 0; s >>= 1) {
        if (t < s) sred[t] += sred[t + s];
        __syncthreads();
    }
    float inv = 1.f / sred[0];
    aw[t] = e0 * inv; aw[256 + t] = e1 * inv;
    __syncthreads();
    if (blockIdx.x == 0 && blockIdx.y == 0) {
        out_full[V + H + t]       = aw[t];
        out_full[V + H + 256 + t] = aw[256 + t];
    }
    int col  = blockIdx.x * 256 + t;
    int base = blockIdx.y * 32;
    float s = 0.f;
    #pragma unroll
    for (int l = 0; l < 32; l++)
        s += aw[base + l] * __ldcs(enc + (size_t)(base + l) * H + col);
    atomicAdd(&g_scratch[OFF_ATT + col], s);
}

// ---------------- N3: x = relu(cat(emb[idx], attn_applied) @ comb_W.T + b) ----------------
__global__ void __launch_bounds__(256)
k_comb(const float* __restrict__ comb_W, const float* __restrict__ comb_b,
       const int* __restrict__ idx, const float* __restrict__ emb) {
    __shared__ float sv[2 * H];
    __shared__ float spart[8];
    int t = threadIdx.x;
    int warp = t >> 5, lane = t & 31;
    int row_e = idx[0];
    #pragma unroll
    for (int i = t; i < 512; i += 256) {
        ((float4*)sv)[i] = (i < 256)
            ? ((const float4*)(emb + (size_t)row_e * H))[i]
            : ((const float4*)(g_scratch + OFF_ATT))[i - 256];
    }
    __syncthreads();
    int row  = blockIdx.x * 4 + (warp >> 1);
    int half = warp & 1;
    const float4* wr = (const float4*)(comb_W + (size_t)row * 2 * H + half * H);
    float acc = warp_sum(dot8(wr, (const float4*)(sv + half * H), lane));
    if (lane == 0) spart[warp] = acc;
    __syncthreads();
    if (t < 4) {
        int r = blockIdx.x * 4 + t;
        g_scratch[OFF_X + r] = fmaxf(spart[2 * t] + spart[2 * t + 1] + comb_b[r], 0.f);
    }
}

// ---------------- N4: mega kernel — gi -> gates -> vocab -> log-softmax ----------------
// 444 blocks = 148 SMs x 3; __launch_bounds__(256,3) guarantees all resident.
#define MB 444
#define MW (MB * 8)    // 3552 warps
__global__ void __launch_bounds__(256, 3)
k_mega(const float* __restrict__ W_ih, const float* __restrict__ b_ih,
       const float* __restrict__ hidden,
       const float* __restrict__ out_W, const float* __restrict__ out_b,
       float* __restrict__ out_full) {
    __shared__ float sbuf[H];
    __shared__ float smax[8];
    __shared__ int s_last;
    int t = threadIdx.x, warp = t >> 5, lane = t & 31;
    int gw = blockIdx.x * 8 + warp;

    // ---- phase 1: gi = x @ W_ih.T + b_ih (one row per warp, rows 0..3071) ----
    ((float4*)sbuf)[t] = ((const float4*)(g_scratch + OFF_X))[t];
    __syncthreads();
    if (gw < 3 * H) {
        const float4* wr = (const float4*)(W_ih + (size_t)gw * H);
        float acc = warp_sum(dot8(wr, (const float4*)sbuf, lane));
        if (lane == 0) g_scratch[OFF_GI + gw] = acc + b_ih[gw];
    }
    __threadfence();
    __syncthreads();
    if (t == 0) atomicAdd(&g_c1, 1);

    // ---- phase 2: GRU gates by blocks 0-3 ----
    if (blockIdx.x < 4) {
        if (t == 0) { while (vpoll(&g_c1) < MB) { } __threadfence(); }
        __syncthreads();
        int j = blockIdx.x * 256 + t;
        float gir = g_scratch[OFF_GI + j],       ghr = g_scratch[OFF_GH + j];
        float giz = g_scratch[OFF_GI + H + j],   ghz = g_scratch[OFF_GH + H + j];
        float gin = g_scratch[OFF_GI + 2*H + j], ghn = g_scratch[OFF_GH + 2*H + j];
        float r = 1.f / (1.f + expf(-(gir + ghr)));
        float z = 1.f / (1.f + expf(-(giz + ghz)));
        float n = tanhf(gin + r * ghn);
        float hn = (1.f - z) * n + z * hidden[j];
        g_scratch[OFF_HNEW + j] = hn;
        out_full[V + j] = hn;                 // second output
        __threadfence();
        __syncthreads();
        if (t == 0) atomicAdd(&g_c2, 1);
    }
    if (t == 0) { while (vpoll(&g_c2) < 4) { } __threadfence(); }
    __syncthreads();

    // ---- phase 3: vocab logits, register-pipelined prefetch ----
    ((float4*)sbuf)[t] = ((const float4*)(g_scratch + OFF_HNEW))[t];
    __syncthreads();
    const float4* v4 = (const float4*)sbuf;
    float m = -INFINITY;
    int row = gw;
    float4 cur[8], nxt[8];
    {
        const float4* wr = (const float4*)(out_W + (size_t)row * H);
        #pragma unroll
        for (int k = 0; k < 8; k++) cur[k] = __ldcs(wr + lane + 32 * k);
    }
    while (row < V) {
        int nrow = row + MW;
        int prow = (nrow < V) ? nrow : 0;      // clamped prefetch (harmless)
        const float4* wn = (const float4*)(out_W + (size_t)prow * H);
        #pragma unroll
        for (int k = 0; k < 8; k++) nxt[k] = __ldcs(wn + lane + 32 * k);

        float a0 = 0.f, a1 = 0.f, a2 = 0.f, a3 = 0.f;
        #pragma unroll
        for (int k = 0; k < 8; k += 4) {
            float4 x0 = v4[lane + 32 * k],       x1 = v4[lane + 32 * (k + 1)];
            float4 x2 = v4[lane + 32 * (k + 2)], x3 = v4[lane + 32 * (k + 3)];
            a0 += cur[k].x*x0.x + cur[k].y*x0.y + cur[k].z*x0.z + cur[k].w*x0.w;
            a1 += cur[k+1].x*x1.x + cur[k+1].y*x1.y + cur[k+1].z*x1.z + cur[k+1].w*x1.w;
            a2 += cur[k+2].x*x2.x + cur[k+2].y*x2.y + cur[k+2].z*x2.z + cur[k+2].w*x2.w;
            a3 += cur[k+3].x*x3.x + cur[k+3].y*x3.y + cur[k+3].z*x3.z + cur[k+3].w*x3.w;
        }
        float acc = warp_sum((a0 + a1) + (a2 + a3));
        if (lane == 0) {
            float r = acc + out_b[row];
            g_scratch[OFF_LOGITS + row] = r;
            m = fmaxf(m, r);
        }
        #pragma unroll
        for (int k = 0; k < 8; k++) cur[k] = nxt[k];
        row = nrow;
    }
    if (lane == 0) smax[warp] = m;
    __threadfence();
    __syncthreads();
    if (t == 0) {
        float bm = smax[0];
        #pragma unroll
        for (int w = 1; w < 8; w++) bm = fmaxf(bm, smax[w]);
        atomicMax(&g_maxbits, f2ord(bm));
        atomicAdd(&g_c3, 1);
        while (vpoll(&g_c3) < MB) { }
        __threadfence();
    }
    __syncthreads();

    // ---- phase 4: log-softmax ----
    float gm = ord2f(g_maxbits);
    {
        __shared__ float sm[256];
        float s = 0.f;
        for (int i = blockIdx.x * 256 + t; i < V; i += MB * 256)
            s += expf(g_scratch[OFF_LOGITS + i] - gm);
        sm[t] = s;
        __syncthreads();
        #pragma unroll
        for (int st = 128; st > 0; st >>= 1) {
            if (t < st) sm[t] += sm[t + st];
            __syncthreads();
        }
        if (t == 0) {
            g_scratch[OFF_PART + blockIdx.x] = sm[0];
            __threadfence();
            int old = atomicAdd(&g_count_ls, 1);
            s_last = (old == MB - 1);
        }
        __syncthreads();
        if (s_last) {
            float p = 0.f;
            for (int i = t; i < MB; i += 256) p += g_scratch[OFF_PART + i];
            sm[t] = p;
            __syncthreads();
            #pragma unroll
            for (int st = 128; st > 0; st >>= 1) {
                if (t < st) sm[t] += sm[t + st];
                __syncthreads();
            }
            if (t == 0) {
                g_scratch[OFF_LSE] = gm + logf(sm[0]);
                __threadfence();
                atomicExch(&g_flag_ls, 1);
            }
        }
        if (t == 0) { while (vpoll(&g_flag_ls) == 0) { } __threadfence(); }
        __syncthreads();
        float lse = g_scratch[OFF_LSE];
        for (int i = blockIdx.x * 256 + t; i < V; i += MB * 256)
            out_full[i] = g_scratch[OFF_LOGITS + i] - lse;
    }
}

// ---------------- launch: 4 graph nodes ----------------
extern "C" void kernel_launch(void* const* d_in, const int* in_sizes, int n_in,
                              void* d_out, int out_size) {
    const int*   input_idx = (const int*)  d_in[0];
    const float* hidden    = (const float*)d_in[1];
    const float* enc       = (const float*)d_in[2];
    const float* emb       = (const float*)d_in[3];
    const float* attn_W    = (const float*)d_in[4];
    const float* attn_b    = (const float*)d_in[5];
    const float* comb_W    = (const float*)d_in[6];
    const float* comb_b    = (const float*)d_in[7];
    const float* W_ih      = (const float*)d_in[8];
    const float* W_hh      = (const float*)d_in[9];
    const float* b_ih      = (const float*)d_in[10];
    const float* b_hh      = (const float*)d_in[11];
    const float* out_W     = (const float*)d_in[12];
    const float* out_b     = (const float*)d_in[13];
    float* out = (float*)d_out;

    k_attn_gh<<<896, 256>>>(attn_W, attn_b, W_hh, b_hh, input_idx, hidden, emb);
    k_apply  <<<dim3(4, 16), 256>>>(enc, out);
    k_comb   <<<256, 256>>>(comb_W, comb_b, input_idx, emb);
    k_mega   <<<MB, 256>>>(W_ih, b_ih, hidden, out_W, out_b, out);
}